// round 1
// baseline (speedup 1.0000x reference)
#include <cuda_runtime.h>
#include <math.h>

#define T 4096
#define BS 128

// ---------------- device scratch (no allocations allowed) ----------------
__device__ float g_S[(size_t)BS * T * 9];   // cumsum of X channels, layout (b, t, 9)
__device__ float g_h[4][T];                 // filter arrays (0=f,1=fp reversed; 2=g,3=gp)
__device__ float g_h0[4];
__device__ int   g_tapm[4][T];              // sparse nonzero-diff taps (ascending m)
__device__ float g_tapv[4][T];
__device__ int   g_tapc[4];

struct FParams {
    const float* W1[4];
    const float* b1[4];
    const float* W2[4];
    const float* b2[4];
};

// ---------------- K1: filter tables + tap compaction ----------------
__global__ void k_filters(FParams p) {
    int tid = threadIdx.x;
    for (int idx = tid; idx < 4 * T; idx += blockDim.x) {
        int f = idx >> 12;
        int i = idx & (T - 1);
        float tt = (f < 2) ? (float)(T - 1 - i) : (float)i;  // f, fp are reversed
        const float* W1 = p.W1[f];
        const float* b1 = p.b1[f];
        const float* W2 = p.W2[f];
        float acc = p.b2[f][0];
        #pragma unroll
        for (int u = 0; u < 5; u++)
            acc += W2[u] * tanhf(W1[u] * tt + b1[u]);
        g_h[f][i] = acc;
    }
    __syncthreads();
    int wid = tid >> 5, lane = tid & 31;
    if (wid < 4) {
        int f = wid;
        if (lane == 0) g_h0[f] = g_h[f][0];
        int cnt = 0;
        for (int base = 1; base < T; base += 32) {
            int m = base + lane;
            float d = 0.f;
            if (m < T) d = g_h[f][m] - g_h[f][m - 1];
            unsigned mask = __ballot_sync(0xffffffffu, d != 0.f);
            if (d != 0.f) {
                int pos = cnt + __popc(mask & ((1u << lane) - 1u));
                g_tapm[f][pos] = m;
                g_tapv[f][pos] = d;
            }
            cnt += __popc(mask);
        }
        if (lane == 0) g_tapc[f] = cnt;
    }
}

// ---------------- K2: Rodrigues + matrix scan + cumsum ----------------
__device__ __forceinline__ void make_E(float z0, float z1,
                                       float a1x, float a1y, float a1z,
                                       float a2x, float a2y, float a2z,
                                       float e[9]) {
    float wx = a1x * z0 + a2x * z1;
    float wy = a1y * z0 + a2y * z1;
    float wz = a1z * z0 + a2z * z1;
    float th2 = wx * wx + wy * wy + wz * wz;
    float s, c, c2;
    if (th2 > 1e-6f) {
        float th = sqrtf(th2);
        float sn, cn;
        sincosf(th, &sn, &cn);
        s = sn / th;
        c = cn;
        c2 = (1.f - cn) / th2;
    } else {
        s = 1.f - th2 * (1.f / 6.f);
        c = 1.f - th2 * 0.5f;
        c2 = 0.5f - th2 * (1.f / 24.f);
    }
    e[0] = c + c2 * wx * wx;      e[1] = c2 * wx * wy - s * wz; e[2] = c2 * wx * wz + s * wy;
    e[3] = c2 * wy * wx + s * wz; e[4] = c + c2 * wy * wy;      e[5] = c2 * wy * wz - s * wx;
    e[6] = c2 * wz * wx - s * wy; e[7] = c2 * wz * wy + s * wx; e[8] = c + c2 * wz * wz;
}

__device__ __forceinline__ void mul_right(float X[9], const float e[9]) {
    #pragma unroll
    for (int r = 0; r < 3; r++) {
        float x0 = X[r * 3], x1 = X[r * 3 + 1], x2 = X[r * 3 + 2];
        X[r * 3 + 0] = x0 * e[0] + x1 * e[3] + x2 * e[6];
        X[r * 3 + 1] = x0 * e[1] + x1 * e[4] + x2 * e[7];
        X[r * 3 + 2] = x0 * e[2] + x1 * e[5] + x2 * e[8];
    }
}

__device__ __forceinline__ void mul_left(float X[9], const float L[9]) {
    // X = L * X
    #pragma unroll
    for (int cc = 0; cc < 3; cc++) {
        float x0 = X[cc], x1 = X[3 + cc], x2 = X[6 + cc];
        X[cc]     = L[0] * x0 + L[1] * x1 + L[2] * x2;
        X[3 + cc] = L[3] * x0 + L[4] * x1 + L[5] * x2;
        X[6 + cc] = L[6] * x0 + L[7] * x1 + L[8] * x2;
    }
}

__global__ void k_pathdev(const float* __restrict__ x_data,
                          const float* __restrict__ A1,
                          const float* __restrict__ A2) {
    __shared__ float sm[256 * 9];
    int b = blockIdx.x, tid = threadIdx.x;
    const float* xb = x_data + (size_t)b * T * 2;

    // skew generators:  A1s[2][1], A1s[0][2], A1s[1][0]
    float a1x = A1[7] - A1[5], a1y = A1[2] - A1[6], a1z = A1[3] - A1[1];
    float a2x = A2[7] - A2[5], a2y = A2[2] - A2[6], a2z = A2[3] - A2[1];

    const int C = T / 256;  // 16
    int t0 = tid * C;

    // pass 1: chunk product
    float P[9] = {1, 0, 0, 0, 1, 0, 0, 0, 1};
    for (int i = 0; i < C; i++) {
        int t = t0 + i;
        if (t > 0) {
            float e[9];
            make_E(xb[2 * t], xb[2 * t + 1], a1x, a1y, a1z, a2x, a2y, a2z, e);
            mul_right(P, e);
        }
    }
    // matrix inclusive scan (Hillis-Steele, order-preserving: left factor is earlier)
    #pragma unroll
    for (int d = 0; d < 9; d++) sm[tid * 9 + d] = P[d];
    for (int off = 1; off < 256; off <<= 1) {
        __syncthreads();
        float L[9];
        int has = tid >= off;
        if (has) {
            #pragma unroll
            for (int d = 0; d < 9; d++) L[d] = sm[(tid - off) * 9 + d];
        }
        __syncthreads();
        if (has) {
            mul_left(P, L);
            #pragma unroll
            for (int d = 0; d < 9; d++) sm[tid * 9 + d] = P[d];
        }
    }
    __syncthreads();
    float PM[9];
    if (tid > 0) {
        #pragma unroll
        for (int d = 0; d < 9; d++) PM[d] = sm[(tid - 1) * 9 + d];
    } else {
        #pragma unroll
        for (int d = 0; d < 9; d++) PM[d] = (d == 0 || d == 4 || d == 8) ? 1.f : 0.f;
    }
    __syncthreads();

    // pass 2: per-chunk channel sums of X
    float X[9], cs[9];
    #pragma unroll
    for (int d = 0; d < 9; d++) { X[d] = PM[d]; cs[d] = 0.f; }
    for (int i = 0; i < C; i++) {
        int t = t0 + i;
        if (t > 0) {
            float e[9];
            make_E(xb[2 * t], xb[2 * t + 1], a1x, a1y, a1z, a2x, a2y, a2z, e);
            mul_right(X, e);
        }
        #pragma unroll
        for (int d = 0; d < 9; d++) cs[d] += X[d];
    }
    // additive inclusive scan of channel sums
    #pragma unroll
    for (int d = 0; d < 9; d++) sm[tid * 9 + d] = cs[d];
    for (int off = 1; off < 256; off <<= 1) {
        __syncthreads();
        float L[9];
        int has = tid >= off;
        if (has) {
            #pragma unroll
            for (int d = 0; d < 9; d++) L[d] = sm[(tid - off) * 9 + d];
        }
        __syncthreads();
        if (has) {
            #pragma unroll
            for (int d = 0; d < 9; d++) { cs[d] += L[d]; sm[tid * 9 + d] = cs[d]; }
        }
    }
    __syncthreads();
    float PS[9];
    if (tid > 0) {
        #pragma unroll
        for (int d = 0; d < 9; d++) PS[d] = sm[(tid - 1) * 9 + d];
    } else {
        #pragma unroll
        for (int d = 0; d < 9; d++) PS[d] = 0.f;
    }

    // pass 3: recompute X per t, emit running cumsum S
    #pragma unroll
    for (int d = 0; d < 9; d++) X[d] = PM[d];
    float* Sb = g_S + ((size_t)b * T) * 9;
    for (int i = 0; i < C; i++) {
        int t = t0 + i;
        if (t > 0) {
            float e[9];
            make_E(xb[2 * t], xb[2 * t + 1], a1x, a1y, a1z, a2x, a2y, a2z, e);
            mul_right(X, e);
        }
        #pragma unroll
        for (int d = 0; d < 9; d++) {
            PS[d] += X[d];
            Sb[(size_t)t * 9 + d] = PS[d];
        }
    }
}

// ---------------- K3: sparse-tap convolutions + combine ----------------
__global__ void k_final(float* __restrict__ out) {
    int half = blockIdx.x, b = blockIdx.y, tid = threadIdx.x;
    int d0 = half ? 5 : 0;
    int ND = half ? 4 : 5;
    extern __shared__ float smem[];
    float* sX  = smem;           // [T][5] cumsum of X channels (this half)
    float* sXi = smem + T * 5;   // [T][5] cumsum of X^T channels (this half)
    const float* Sb = g_S + ((size_t)b * T) * 9;

    for (int idx = tid; idx < T * ND; idx += blockDim.x) {
        int t = idx / ND, j = idx - t * ND;
        int d = d0 + j;
        int dsw = (d % 3) * 3 + d / 3;  // transpose channel map
        sX[t * 5 + j]  = Sb[(size_t)t * 9 + d];
        sXi[t * 5 + j] = Sb[(size_t)t * 9 + dsw];
    }
    __syncthreads();

    float h0f = g_h0[0], h0fp = g_h0[1], h0g = g_h0[2], h0gp = g_h0[3];
    int nf = g_tapc[0], nfp = g_tapc[1], ng = g_tapc[2], ngp = g_tapc[3];

    for (int k = tid; k < T; k += blockDim.x) {
        for (int j = 0; j < ND; j++) {
            float sxi = sXi[k * 5 + j], sx = sX[k * 5 + j];
            float aF = h0f * sxi, aFp = h0fp * sxi;
            float aG = h0g * sx,  aGp = h0gp * sx;
            for (int l = 0; l < nf; l++) {
                int m = g_tapm[0][l];
                if (m > k) break;
                aF += g_tapv[0][l] * sXi[(k - m) * 5 + j];
            }
            for (int l = 0; l < nfp; l++) {
                int m = g_tapm[1][l];
                if (m > k) break;
                aFp += g_tapv[1][l] * sXi[(k - m) * 5 + j];
            }
            for (int l = 0; l < ng; l++) {
                int m = g_tapm[2][l];
                if (m > k) break;
                aG += g_tapv[2][l] * sX[(k - m) * 5 + j];
            }
            for (int l = 0; l < ngp; l++) {
                int m = g_tapm[3][l];
                if (m > k) break;
                aGp += g_tapv[3][l] * sX[(k - m) * 5 + j];
            }
            out[((size_t)b * T + k) * 9 + d0 + j] = aF * aG + aFp * aGp;
        }
    }
}

// ---------------- launch ----------------
extern "C" void kernel_launch(void* const* d_in, const int* in_sizes, int n_in,
                              void* d_out, int out_size) {
    (void)in_sizes; (void)n_in; (void)out_size;
    const float* x  = (const float*)d_in[0];
    const float* A1 = (const float*)d_in[1];
    const float* A2 = (const float*)d_in[2];
    FParams p;
    for (int f = 0; f < 4; f++) {
        p.W1[f] = (const float*)d_in[3 + 4 * f + 0];
        p.b1[f] = (const float*)d_in[3 + 4 * f + 1];
        p.W2[f] = (const float*)d_in[3 + 4 * f + 2];
        p.b2[f] = (const float*)d_in[3 + 4 * f + 3];
    }

    k_filters<<<1, 1024>>>(p);
    k_pathdev<<<BS, 256>>>(x, A1, A2);

    const int SMEM = 2 * T * 5 * (int)sizeof(float);  // 163,840 B
    cudaFuncSetAttribute(k_final, cudaFuncAttributeMaxDynamicSharedMemorySize, SMEM);
    k_final<<<dim3(2, BS), 1024, SMEM>>>((float*)d_out);
}

// round 2
// speedup vs baseline: 5.4388x; 5.4388x over previous
#include <cuda_runtime.h>
#include <math.h>

#define T 4096
#define BS 128
#define CAPT 2048          // per-list shared tap cache (float4 entries)

typedef unsigned long long ull;

// ---------------- device scratch (no allocations allowed) ----------------
__device__ float  g_S[(size_t)BS * T * 10];   // cumsum of X channels, padded rows (b, t, 10)
__device__ float  g_h[4][T];                  // filter arrays (0=f,1=fp reversed; 2=g,3=gp)
__device__ float4 g_Ftap[T + 8];              // merged (m, df, dfp, 0), ascending m, +sentinels
__device__ float4 g_Gtap[T + 8];              // merged (m, dg, dgp, 0)
__device__ int    g_nF, g_nG;

struct FParams {
    const float* W1[4];
    const float* b1[4];
    const float* W2[4];
    const float* b2[4];
};

// ---------------- K1: filter tables + merged tap-pair compaction ----------------
__global__ void k_filters(FParams p) {
    int tid = threadIdx.x;
    for (int idx = tid; idx < 4 * T; idx += blockDim.x) {
        int f = idx >> 12;
        int i = idx & (T - 1);
        float tt = (f < 2) ? (float)(T - 1 - i) : (float)i;  // f, fp are reversed
        const float* W1 = p.W1[f];
        const float* b1 = p.b1[f];
        const float* W2 = p.W2[f];
        float acc = p.b2[f][0];
        #pragma unroll
        for (int u = 0; u < 5; u++)
            acc += W2[u] * tanhf(W1[u] * tt + b1[u]);
        g_h[f][i] = acc;
    }
    __syncthreads();
    int wid = tid >> 5, lane = tid & 31;
    if (wid < 2) {
        // wid 0 -> pair (0,1) into g_Ftap ; wid 1 -> pair (2,3) into g_Gtap
        int fa = wid * 2, fb = fa + 1;
        float4* dst = wid ? g_Gtap : g_Ftap;
        int cnt = 0;
        for (int base = 0; base < T; base += 32) {
            int m = base + lane;
            float da = (m == 0) ? g_h[fa][0] : g_h[fa][m] - g_h[fa][m - 1];
            float db = (m == 0) ? g_h[fb][0] : g_h[fb][m] - g_h[fb][m - 1];
            int act = (da != 0.f) || (db != 0.f);
            unsigned mask = __ballot_sync(0xffffffffu, act);
            if (act) {
                int pos = cnt + __popc(mask & ((1u << lane) - 1u));
                dst[pos] = make_float4(__int_as_float(m), da, db, 0.f);
            }
            cnt += __popc(mask);
        }
        // sentinels
        if (lane < 8)
            dst[cnt + lane] = make_float4(__int_as_float(0x7fffffff), 0.f, 0.f, 0.f);
        if (lane == 0) {
            if (wid == 0) g_nF = cnt; else g_nG = cnt;
        }
    }
}

// ---------------- K2: Rodrigues + matrix scan + double-precision cumsum ----------------
__device__ __forceinline__ void make_E(float z0, float z1,
                                       float a1x, float a1y, float a1z,
                                       float a2x, float a2y, float a2z,
                                       float e[9]) {
    float wx = a1x * z0 + a2x * z1;
    float wy = a1y * z0 + a2y * z1;
    float wz = a1z * z0 + a2z * z1;
    float th2 = wx * wx + wy * wy + wz * wz;
    float s, c, c2;
    if (th2 > 1e-6f) {
        float th = sqrtf(th2);
        float sn, cn;
        sincosf(th, &sn, &cn);
        s = sn / th;
        c = cn;
        c2 = (1.f - cn) / th2;
    } else {
        s = 1.f - th2 * (1.f / 6.f);
        c = 1.f - th2 * 0.5f;
        c2 = 0.5f - th2 * (1.f / 24.f);
    }
    e[0] = c + c2 * wx * wx;      e[1] = c2 * wx * wy - s * wz; e[2] = c2 * wx * wz + s * wy;
    e[3] = c2 * wy * wx + s * wz; e[4] = c + c2 * wy * wy;      e[5] = c2 * wy * wz - s * wx;
    e[6] = c2 * wz * wx - s * wy; e[7] = c2 * wz * wy + s * wx; e[8] = c + c2 * wz * wz;
}

__device__ __forceinline__ void mul_right(float X[9], const float e[9]) {
    #pragma unroll
    for (int r = 0; r < 3; r++) {
        float x0 = X[r * 3], x1 = X[r * 3 + 1], x2 = X[r * 3 + 2];
        X[r * 3 + 0] = x0 * e[0] + x1 * e[3] + x2 * e[6];
        X[r * 3 + 1] = x0 * e[1] + x1 * e[4] + x2 * e[7];
        X[r * 3 + 2] = x0 * e[2] + x1 * e[5] + x2 * e[8];
    }
}

__device__ __forceinline__ void mul_left(float X[9], const float L[9]) {
    #pragma unroll
    for (int cc = 0; cc < 3; cc++) {
        float x0 = X[cc], x1 = X[3 + cc], x2 = X[6 + cc];
        X[cc]     = L[0] * x0 + L[1] * x1 + L[2] * x2;
        X[3 + cc] = L[3] * x0 + L[4] * x1 + L[5] * x2;
        X[6 + cc] = L[6] * x0 + L[7] * x1 + L[8] * x2;
    }
}

__global__ void k_pathdev(const float* __restrict__ x_data,
                          const float* __restrict__ A1,
                          const float* __restrict__ A2) {
    __shared__ double smd[256 * 9];     // used as float* for matrix scan, double for additive
    float* smf = (float*)smd;
    int b = blockIdx.x, tid = threadIdx.x;
    const float* xb = x_data + (size_t)b * T * 2;

    float a1x = A1[7] - A1[5], a1y = A1[2] - A1[6], a1z = A1[3] - A1[1];
    float a2x = A2[7] - A2[5], a2y = A2[2] - A2[6], a2z = A2[3] - A2[1];

    const int C = T / 256;  // 16
    int t0 = tid * C;

    // pass 1: chunk product
    float P[9] = {1, 0, 0, 0, 1, 0, 0, 0, 1};
    for (int i = 0; i < C; i++) {
        int t = t0 + i;
        if (t > 0) {
            float e[9];
            make_E(xb[2 * t], xb[2 * t + 1], a1x, a1y, a1z, a2x, a2y, a2z, e);
            mul_right(P, e);
        }
    }
    #pragma unroll
    for (int d = 0; d < 9; d++) smf[tid * 9 + d] = P[d];
    for (int off = 1; off < 256; off <<= 1) {
        __syncthreads();
        float L[9];
        int has = tid >= off;
        if (has) {
            #pragma unroll
            for (int d = 0; d < 9; d++) L[d] = smf[(tid - off) * 9 + d];
        }
        __syncthreads();
        if (has) {
            mul_left(P, L);
            #pragma unroll
            for (int d = 0; d < 9; d++) smf[tid * 9 + d] = P[d];
        }
    }
    __syncthreads();
    float PM[9];
    if (tid > 0) {
        #pragma unroll
        for (int d = 0; d < 9; d++) PM[d] = smf[(tid - 1) * 9 + d];
    } else {
        #pragma unroll
        for (int d = 0; d < 9; d++) PM[d] = (d == 0 || d == 4 || d == 8) ? 1.f : 0.f;
    }
    __syncthreads();

    // pass 2: per-chunk channel sums of X (double)
    float X[9];
    double cs[9];
    #pragma unroll
    for (int d = 0; d < 9; d++) { X[d] = PM[d]; cs[d] = 0.0; }
    for (int i = 0; i < C; i++) {
        int t = t0 + i;
        if (t > 0) {
            float e[9];
            make_E(xb[2 * t], xb[2 * t + 1], a1x, a1y, a1z, a2x, a2y, a2z, e);
            mul_right(X, e);
        }
        #pragma unroll
        for (int d = 0; d < 9; d++) cs[d] += (double)X[d];
    }
    #pragma unroll
    for (int d = 0; d < 9; d++) smd[tid * 9 + d] = cs[d];
    for (int off = 1; off < 256; off <<= 1) {
        __syncthreads();
        double L[9];
        int has = tid >= off;
        if (has) {
            #pragma unroll
            for (int d = 0; d < 9; d++) L[d] = smd[(tid - off) * 9 + d];
        }
        __syncthreads();
        if (has) {
            #pragma unroll
            for (int d = 0; d < 9; d++) { cs[d] += L[d]; smd[tid * 9 + d] = cs[d]; }
        }
    }
    __syncthreads();
    double PS[9];
    if (tid > 0) {
        #pragma unroll
        for (int d = 0; d < 9; d++) PS[d] = smd[(tid - 1) * 9 + d];
    } else {
        #pragma unroll
        for (int d = 0; d < 9; d++) PS[d] = 0.0;
    }

    // pass 3: recompute X, emit running cumsum S (padded rows of 10)
    #pragma unroll
    for (int d = 0; d < 9; d++) X[d] = PM[d];
    float* Sb = g_S + (size_t)b * T * 10;
    for (int i = 0; i < C; i++) {
        int t = t0 + i;
        if (t > 0) {
            float e[9];
            make_E(xb[2 * t], xb[2 * t + 1], a1x, a1y, a1z, a2x, a2y, a2z, e);
            mul_right(X, e);
        }
        #pragma unroll
        for (int d = 0; d < 9; d++) {
            PS[d] += (double)X[d];
            Sb[(size_t)t * 10 + d] = (float)PS[d];
        }
        Sb[(size_t)t * 10 + 9] = 0.f;
    }
}

// ---------------- K3: packed-FMA sparse-tap convolutions + combine ----------------
__device__ __forceinline__ ull packf(float a) {
    ull r;
    asm("mov.b64 %0, {%1, %1};" : "=l"(r) : "f"(a));
    return r;
}
__device__ __forceinline__ ull f2bits(float2 v) {
    ull r;
    asm("mov.b64 %0, {%1, %2};" : "=l"(r) : "f"(v.x), "f"(v.y));
    return r;
}
__device__ __forceinline__ void fma2(ull& acc, ull a, ull b) {
    asm("fma.rn.f32x2 %0, %1, %2, %0;" : "+l"(acc) : "l"(a), "l"(b));
}
__device__ __forceinline__ void unpck(ull v, float& lo, float& hi) {
    asm("mov.b64 {%0, %1}, %2;" : "=f"(lo), "=f"(hi) : "l"(v));
}

template <bool SH>
__device__ __forceinline__ void run_list(const float4* __restrict__ taps, int n,
                                         int k, int kmax,
                                         const float* __restrict__ sS,
                                         ull a1[5], ull a2[5]) {
    for (int l = 0; l < n; l += 2) {
        float4 t0 = SH ? taps[l] : __ldg(&taps[l]);
        int m0 = __float_as_int(t0.x);
        if (m0 > kmax) break;
        float4 t1 = SH ? taps[l + 1] : __ldg(&taps[l + 1]);
        int m1 = __float_as_int(t1.x);

        {
            bool act = m0 <= k;
            int r = act ? (k - m0) : 0;
            ull v1 = packf(act ? t0.y : 0.f);
            ull v2 = packf(act ? t0.z : 0.f);
            const float2* row = (const float2*)(sS + r * 10);
            #pragma unroll
            for (int c = 0; c < 5; c++) {
                ull d = f2bits(row[c]);
                fma2(a1[c], d, v1);
                fma2(a2[c], d, v2);
            }
        }
        {
            bool act = m1 <= k;
            int r = act ? (k - m1) : 0;
            ull v1 = packf(act ? t1.y : 0.f);
            ull v2 = packf(act ? t1.z : 0.f);
            const float2* row = (const float2*)(sS + r * 10);
            #pragma unroll
            for (int c = 0; c < 5; c++) {
                ull d = f2bits(row[c]);
                fma2(a1[c], d, v1);
                fma2(a2[c], d, v2);
            }
        }
    }
}

__global__ void __launch_bounds__(512, 1) k_final(float* __restrict__ out) {
    extern __shared__ __align__(16) float smem[];
    float*  sS    = smem;                          // up to 4096*10 floats
    float4* sTapF = (float4*)(smem + T * 10);      // CAPT entries
    float4* sTapG = sTapF + CAPT;

    int q = blockIdx.x, b = blockIdx.y, tid = threadIdx.x;
    int k = q * 512 + tid;
    int khi = q * 512 + 511;
    int nrows = khi + 1;

    // stage S rows [0, khi]
    {
        const float2* src = (const float2*)(g_S + (size_t)b * T * 10);
        float2* dst = (float2*)sS;
        int n2 = nrows * 5;
        for (int i = tid; i < n2; i += 512) dst[i] = src[i];
    }
    int nF = g_nF, nG = g_nG;
    bool fitF = (nF + 8) <= CAPT;
    bool fitG = (nG + 8) <= CAPT;
    if (fitF) for (int i = tid; i < nF + 8; i += 512) sTapF[i] = g_Ftap[i];
    if (fitG) for (int i = tid; i < nG + 8; i += 512) sTapG[i] = g_Gtap[i];
    __syncthreads();

    int kmax = k | 31;
    ull aF[5], aFp[5], aG[5], aGp[5];
    #pragma unroll
    for (int c = 0; c < 5; c++) { aF[c] = 0; aFp[c] = 0; aG[c] = 0; aGp[c] = 0; }

    if (fitF) run_list<true >(sTapF,  nF, k, kmax, sS, aF, aFp);
    else      run_list<false>(g_Ftap, nF, k, kmax, sS, aF, aFp);
    if (fitG) run_list<true >(sTapG,  nG, k, kmax, sS, aG, aGp);
    else      run_list<false>(g_Gtap, nG, k, kmax, sS, aG, aGp);

    float bF[10], bFp[10], bG[10], bGp[10];
    #pragma unroll
    for (int c = 0; c < 5; c++) {
        unpck(aF[c],  bF[2 * c],  bF[2 * c + 1]);
        unpck(aFp[c], bFp[2 * c], bFp[2 * c + 1]);
        unpck(aG[c],  bG[2 * c],  bG[2 * c + 1]);
        unpck(aGp[c], bGp[2 * c], bGp[2 * c + 1]);
    }

    float res[9];
    #pragma unroll
    for (int i = 0; i < 3; i++)
        #pragma unroll
        for (int j = 0; j < 3; j++) {
            int d = 3 * i + j, dt = 3 * j + i;
            res[d] = bF[dt] * bG[d] + bFp[dt] * bGp[d];
        }

    // coalesced store via shared staging (reuse tap cache region)
    __syncthreads();
    float* sOut = (float*)sTapF;
    #pragma unroll
    for (int d = 0; d < 9; d++) sOut[tid * 9 + d] = res[d];
    __syncthreads();
    float4* o4 = (float4*)(out + ((size_t)b * T + (size_t)q * 512) * 9);
    const float4* s4 = (const float4*)sOut;
    for (int i = tid; i < 512 * 9 / 4; i += 512) o4[i] = s4[i];
}

// ---------------- launch ----------------
extern "C" void kernel_launch(void* const* d_in, const int* in_sizes, int n_in,
                              void* d_out, int out_size) {
    (void)in_sizes; (void)n_in; (void)out_size;
    const float* x  = (const float*)d_in[0];
    const float* A1 = (const float*)d_in[1];
    const float* A2 = (const float*)d_in[2];
    FParams p;
    for (int f = 0; f < 4; f++) {
        p.W1[f] = (const float*)d_in[3 + 4 * f + 0];
        p.b1[f] = (const float*)d_in[3 + 4 * f + 1];
        p.W2[f] = (const float*)d_in[3 + 4 * f + 2];
        p.b2[f] = (const float*)d_in[3 + 4 * f + 3];
    }

    k_filters<<<1, 1024>>>(p);
    k_pathdev<<<BS, 256>>>(x, A1, A2);

    const int SMEM = T * 10 * 4 + 2 * CAPT * 16;  // 163840 + 65536 = 229376 B
    cudaFuncSetAttribute(k_final, cudaFuncAttributeMaxDynamicSharedMemorySize, SMEM);
    k_final<<<dim3(8, BS), 512, SMEM>>>((float*)d_out);
}

// round 3
// speedup vs baseline: 6.8348x; 1.2567x over previous
#include <cuda_runtime.h>
#include <math.h>

#define T 4096
#define BS 128
#define CAPT 1024          // per-list shared tap cache (float4 entries)

typedef unsigned long long ull;

// ---------------- device scratch (no allocations allowed) ----------------
__device__ float2 g_S2[(size_t)BS * 5 * T];   // cumsum of X, transposed: (b, ch-pair, t)
__device__ float4 g_Ftap[T + 8];              // merged (m, df, dfp, 0), ascending m, +sentinels
__device__ float4 g_Gtap[T + 8];              // merged (m, dg, dgp, 0)
__device__ int    g_nF, g_nG;

struct FParams {
    const float* W1[4];
    const float* b1[4];
    const float* W2[4];
    const float* b2[4];
};

// ---------------- math helpers ----------------
__device__ __forceinline__ void make_E(float z0, float z1,
                                       float a1x, float a1y, float a1z,
                                       float a2x, float a2y, float a2z,
                                       float e[9]) {
    float wx = a1x * z0 + a2x * z1;
    float wy = a1y * z0 + a2y * z1;
    float wz = a1z * z0 + a2z * z1;
    float th2 = wx * wx + wy * wy + wz * wz;
    float s, c, c2;
    if (th2 > 1e-6f) {
        float th = sqrtf(th2);
        float sn, cn;
        sincosf(th, &sn, &cn);
        s = sn / th;
        c = cn;
        c2 = (1.f - cn) / th2;
    } else {
        s = 1.f - th2 * (1.f / 6.f);
        c = 1.f - th2 * 0.5f;
        c2 = 0.5f - th2 * (1.f / 24.f);
    }
    e[0] = c + c2 * wx * wx;      e[1] = c2 * wx * wy - s * wz; e[2] = c2 * wx * wz + s * wy;
    e[3] = c2 * wy * wx + s * wz; e[4] = c + c2 * wy * wy;      e[5] = c2 * wy * wz - s * wx;
    e[6] = c2 * wz * wx - s * wy; e[7] = c2 * wz * wy + s * wx; e[8] = c + c2 * wz * wz;
}

__device__ __forceinline__ void mul_right(float X[9], const float e[9]) {
    #pragma unroll
    for (int r = 0; r < 3; r++) {
        float x0 = X[r * 3], x1 = X[r * 3 + 1], x2 = X[r * 3 + 2];
        X[r * 3 + 0] = x0 * e[0] + x1 * e[3] + x2 * e[6];
        X[r * 3 + 1] = x0 * e[1] + x1 * e[4] + x2 * e[7];
        X[r * 3 + 2] = x0 * e[2] + x1 * e[5] + x2 * e[8];
    }
}

__device__ __forceinline__ void mul_left(float X[9], const float L[9]) {
    #pragma unroll
    for (int cc = 0; cc < 3; cc++) {
        float x0 = X[cc], x1 = X[3 + cc], x2 = X[6 + cc];
        X[cc]     = L[0] * x0 + L[1] * x1 + L[2] * x2;
        X[3 + cc] = L[3] * x0 + L[4] * x1 + L[5] * x2;
        X[6 + cc] = L[6] * x0 + L[7] * x1 + L[8] * x2;
    }
}

// ---------------- K_main: filters block (bid==BS) + pathdev blocks ----------------
__global__ void __launch_bounds__(256) k_main(const float* __restrict__ x_data,
                                              const float* __restrict__ A1,
                                              const float* __restrict__ A2,
                                              FParams p) {
    extern __shared__ float smem[];
    int tid = threadIdx.x;

    if (blockIdx.x == BS) {
        // ---- filter tables in shared, then warp compaction from shared ----
        float* sh = smem;  // [4][T] = 64 KB
        for (int idx = tid; idx < 4 * T; idx += 256) {
            int f = idx >> 12;
            int i = idx & (T - 1);
            float tt = (f < 2) ? (float)(T - 1 - i) : (float)i;  // f, fp reversed
            const float* W1 = p.W1[f];
            const float* b1 = p.b1[f];
            const float* W2 = p.W2[f];
            float acc = p.b2[f][0];
            #pragma unroll
            for (int u = 0; u < 5; u++)
                acc += W2[u] * tanhf(W1[u] * tt + b1[u]);
            sh[f * T + i] = acc;
        }
        __syncthreads();
        int wid = tid >> 5, lane = tid & 31;
        if (wid < 2) {
            int fa = wid * 2, fb = fa + 1;
            float4* dst = wid ? g_Gtap : g_Ftap;
            int cnt = 0;
            for (int base = 0; base < T; base += 32) {
                int m = base + lane;
                float da = (m == 0) ? sh[fa * T] : sh[fa * T + m] - sh[fa * T + m - 1];
                float db = (m == 0) ? sh[fb * T] : sh[fb * T + m] - sh[fb * T + m - 1];
                int act = (da != 0.f) || (db != 0.f);
                unsigned mask = __ballot_sync(0xffffffffu, act);
                if (act) {
                    int pos = cnt + __popc(mask & ((1u << lane) - 1u));
                    dst[pos] = make_float4(__int_as_float(m), da, db, 0.f);
                }
                cnt += __popc(mask);
            }
            if (lane < 8)
                dst[cnt + lane] = make_float4(__int_as_float(0x7fffffff), 0.f, 0.f, 0.f);
            if (lane == 0) {
                if (wid == 0) g_nF = cnt; else g_nG = cnt;
            }
        }
        return;
    }

    // ---- pathdev block ----
    float* sx  = smem;          // 8192 floats: x staged (t, 2)
    float* smf = smem + 8192;   // 256*9 floats scan region
    int b = blockIdx.x;

    // stage x coalesced
    {
        const float4* src = (const float4*)(x_data + (size_t)b * T * 2);
        float4* dst = (float4*)sx;
        #pragma unroll
        for (int i = tid; i < T * 2 / 4; i += 256) dst[i] = src[i];
    }

    float a1x = A1[7] - A1[5], a1y = A1[2] - A1[6], a1z = A1[3] - A1[1];
    float a2x = A2[7] - A2[5], a2y = A2[2] - A2[6], a2z = A2[3] - A2[1];
    __syncthreads();

    const int C = T / 256;  // 16
    int t0 = tid * C;

    // pass 1: chunk product P_loc AND chunk-local channel sums CS_loc (linearity)
    float P[9] = {1, 0, 0, 0, 1, 0, 0, 0, 1};
    float CS[9] = {0, 0, 0, 0, 0, 0, 0, 0, 0};
    for (int i = 0; i < C; i++) {
        int t = t0 + i;
        if (t > 0) {
            float e[9];
            make_E(sx[2 * t], sx[2 * t + 1], a1x, a1y, a1z, a2x, a2y, a2z, e);
            mul_right(P, e);
        }
        #pragma unroll
        for (int d = 0; d < 9; d++) CS[d] += P[d];
    }

    // matrix inclusive scan of chunk products
    float Pw[9];
    #pragma unroll
    for (int d = 0; d < 9; d++) { Pw[d] = P[d]; smf[tid * 9 + d] = P[d]; }
    for (int off = 1; off < 256; off <<= 1) {
        __syncthreads();
        float L[9];
        int has = tid >= off;
        if (has) {
            #pragma unroll
            for (int d = 0; d < 9; d++) L[d] = smf[(tid - off) * 9 + d];
        }
        __syncthreads();
        if (has) {
            mul_left(Pw, L);
            #pragma unroll
            for (int d = 0; d < 9; d++) smf[tid * 9 + d] = Pw[d];
        }
    }
    __syncthreads();
    float PM[9];
    if (tid > 0) {
        #pragma unroll
        for (int d = 0; d < 9; d++) PM[d] = smf[(tid - 1) * 9 + d];
    } else {
        #pragma unroll
        for (int d = 0; d < 9; d++) PM[d] = (d == 0 || d == 4 || d == 8) ? 1.f : 0.f;
    }
    __syncthreads();

    // global chunk channel-sum = PM (3x3) * CS_loc (3x3)
    float CSg[9];
    #pragma unroll
    for (int i = 0; i < 3; i++)
        #pragma unroll
        for (int j = 0; j < 3; j++)
            CSg[3 * i + j] = PM[3 * i + 0] * CS[0 + j] + PM[3 * i + 1] * CS[3 + j] + PM[3 * i + 2] * CS[6 + j];

    // additive inclusive scan of CSg
    float Aw[9];
    #pragma unroll
    for (int d = 0; d < 9; d++) { Aw[d] = CSg[d]; smf[tid * 9 + d] = CSg[d]; }
    for (int off = 1; off < 256; off <<= 1) {
        __syncthreads();
        float L[9];
        int has = tid >= off;
        if (has) {
            #pragma unroll
            for (int d = 0; d < 9; d++) L[d] = smf[(tid - off) * 9 + d];
        }
        __syncthreads();
        if (has) {
            #pragma unroll
            for (int d = 0; d < 9; d++) { Aw[d] += L[d]; smf[tid * 9 + d] = Aw[d]; }
        }
    }
    __syncthreads();
    float PS[9];
    if (tid > 0) {
        #pragma unroll
        for (int d = 0; d < 9; d++) PS[d] = smf[(tid - 1) * 9 + d];
    } else {
        #pragma unroll
        for (int d = 0; d < 9; d++) PS[d] = 0.f;
    }

    // pass 2 (final): recompute X per t, emit running cumsum to transposed g_S2
    float X[9];
    #pragma unroll
    for (int d = 0; d < 9; d++) X[d] = PM[d];
    float2* Sb = g_S2 + (size_t)b * 5 * T;
    for (int i = 0; i < C; i++) {
        int t = t0 + i;
        if (t > 0) {
            float e[9];
            make_E(sx[2 * t], sx[2 * t + 1], a1x, a1y, a1z, a2x, a2y, a2z, e);
            mul_right(X, e);
        }
        #pragma unroll
        for (int d = 0; d < 9; d++) PS[d] += X[d];
        Sb[0 * T + t] = make_float2(PS[0], PS[1]);
        Sb[1 * T + t] = make_float2(PS[2], PS[3]);
        Sb[2 * T + t] = make_float2(PS[4], PS[5]);
        Sb[3 * T + t] = make_float2(PS[6], PS[7]);
        Sb[4 * T + t] = make_float2(PS[8], 0.f);
    }
}

// ---------------- K_final: packed-FMA taps, transposed smem, 2 k per thread ----------------
__device__ __forceinline__ ull packf(float a) {
    ull r;
    asm("mov.b64 %0, {%1, %1};" : "=l"(r) : "f"(a));
    return r;
}
__device__ __forceinline__ ull f2bits(float2 v) {
    ull r;
    asm("mov.b64 %0, {%1, %2};" : "=l"(r) : "f"(v.x), "f"(v.y));
    return r;
}
__device__ __forceinline__ void fma2(ull& acc, ull a, ull b) {
    asm("fma.rn.f32x2 %0, %1, %2, %0;" : "+l"(acc) : "l"(a), "l"(b));
}
__device__ __forceinline__ void unpck(ull v, float& lo, float& hi) {
    asm("mov.b64 {%0, %1}, %2;" : "=f"(lo), "=f"(hi) : "l"(v));
}

template <bool SH>
__device__ __forceinline__ void run_list(const float4* __restrict__ taps, int n,
                                         int k1, int k2, int kmax2,
                                         const float2* __restrict__ sS,
                                         ull aA1[5], ull aB1[5], ull aA2[5], ull aB2[5]) {
    for (int l = 0; l < n; l += 2) {
        float4 tp0 = SH ? taps[l] : __ldg(&taps[l]);
        int m0 = __float_as_int(tp0.x);
        if (m0 > kmax2) break;
        float4 tp1 = SH ? taps[l + 1] : __ldg(&taps[l + 1]);
        int m1 = __float_as_int(tp1.x);

        #pragma unroll
        for (int s = 0; s < 2; s++) {
            float4 tp = s ? tp1 : tp0;
            int m = s ? m1 : m0;
            bool b1a = m <= k1, b2a = m <= k2;
            int r1 = b1a ? (k1 - m) : 0;
            int r2 = b2a ? (k2 - m) : 0;
            ull vy1 = packf(b1a ? tp.y : 0.f);
            ull vz1 = packf(b1a ? tp.z : 0.f);
            ull vy2 = packf(b2a ? tp.y : 0.f);
            ull vz2 = packf(b2a ? tp.z : 0.f);
            #pragma unroll
            for (int c = 0; c < 5; c++) {
                ull d1 = f2bits(sS[c * T + r1]);
                ull d2 = f2bits(sS[c * T + r2]);
                fma2(aA1[c], d1, vy1);
                fma2(aB1[c], d1, vz1);
                fma2(aA2[c], d2, vy2);
                fma2(aB2[c], d2, vz2);
            }
        }
    }
}

__global__ void __launch_bounds__(256, 1) k_final(float* __restrict__ out) {
    extern __shared__ __align__(16) float smem[];
    float2* sS    = (float2*)smem;                     // 5 planes x T float2 (163840 B)
    float4* sTapF = (float4*)(smem + 5 * T * 2);       // CAPT+8 entries
    float4* sTapG = sTapF + (CAPT + 8);

    int q = blockIdx.x, b = blockIdx.y, tid = threadIdx.x;
    int k1 = q * 512 + tid;
    int k2 = k1 + 256;
    int khi = q * 512 + 511;
    int nrows = khi + 1;

    // stage S planes [0, khi], coalesced float4
    {
        const float2* src = g_S2 + (size_t)b * 5 * T;
        #pragma unroll
        for (int pp = 0; pp < 5; pp++) {
            float4* d4 = (float4*)(sS + pp * T);
            const float4* s4 = (const float4*)(src + pp * T);
            for (int i = tid; i < nrows / 2; i += 256) d4[i] = s4[i];
        }
    }
    int nF = g_nF, nG = g_nG;
    bool fitF = (nF + 8) <= CAPT + 8;
    bool fitG = (nG + 8) <= CAPT + 8;
    if (fitF) for (int i = tid; i < nF + 8; i += 256) sTapF[i] = g_Ftap[i];
    if (fitG) for (int i = tid; i < nG + 8; i += 256) sTapG[i] = g_Gtap[i];
    __syncthreads();

    int kmax2 = (k1 | 31) + 256;
    ull aF1[5], aFp1[5], aG1[5], aGp1[5];
    ull aF2[5], aFp2[5], aG2[5], aGp2[5];
    #pragma unroll
    for (int c = 0; c < 5; c++) {
        aF1[c] = 0; aFp1[c] = 0; aG1[c] = 0; aGp1[c] = 0;
        aF2[c] = 0; aFp2[c] = 0; aG2[c] = 0; aGp2[c] = 0;
    }

    if (fitF) run_list<true >(sTapF,  nF, k1, k2, kmax2, sS, aF1, aFp1, aF2, aFp2);
    else      run_list<false>(g_Ftap, nF, k1, k2, kmax2, sS, aF1, aFp1, aF2, aFp2);
    if (fitG) run_list<true >(sTapG,  nG, k1, k2, kmax2, sS, aG1, aGp1, aG2, aGp2);
    else      run_list<false>(g_Gtap, nG, k1, k2, kmax2, sS, aG1, aGp1, aG2, aGp2);

    // combine + stage output (reuse tap region after sync)
    __syncthreads();
    float* sOut = (float*)sTapF;   // 512*9 floats = 18432 B < tap area

    #pragma unroll
    for (int h = 0; h < 2; h++) {
        float bF[10], bFp[10], bG[10], bGp[10];
        #pragma unroll
        for (int c = 0; c < 5; c++) {
            unpck(h ? aF2[c]  : aF1[c],  bF[2 * c],  bF[2 * c + 1]);
            unpck(h ? aFp2[c] : aFp1[c], bFp[2 * c], bFp[2 * c + 1]);
            unpck(h ? aG2[c]  : aG1[c],  bG[2 * c],  bG[2 * c + 1]);
            unpck(h ? aGp2[c] : aGp1[c], bGp[2 * c], bGp[2 * c + 1]);
        }
        int row = h * 256 + tid;
        #pragma unroll
        for (int i = 0; i < 3; i++)
            #pragma unroll
            for (int j = 0; j < 3; j++) {
                int d = 3 * i + j, dt = 3 * j + i;
                sOut[row * 9 + d] = bF[dt] * bG[d] + bFp[dt] * bGp[d];
            }
    }
    __syncthreads();

    float4* o4 = (float4*)(out + ((size_t)b * T + (size_t)q * 512) * 9);
    const float4* s4 = (const float4*)sOut;
    #pragma unroll
    for (int i = tid; i < 512 * 9 / 4; i += 256) o4[i] = s4[i];
}

// ---------------- launch ----------------
extern "C" void kernel_launch(void* const* d_in, const int* in_sizes, int n_in,
                              void* d_out, int out_size) {
    (void)in_sizes; (void)n_in; (void)out_size;
    const float* x  = (const float*)d_in[0];
    const float* A1 = (const float*)d_in[1];
    const float* A2 = (const float*)d_in[2];
    FParams p;
    for (int f = 0; f < 4; f++) {
        p.W1[f] = (const float*)d_in[3 + 4 * f + 0];
        p.b1[f] = (const float*)d_in[3 + 4 * f + 1];
        p.W2[f] = (const float*)d_in[3 + 4 * f + 2];
        p.b2[f] = (const float*)d_in[3 + 4 * f + 3];
    }

    const int SM1 = 4 * T * (int)sizeof(float);  // 65536 (filters block); pathdev uses 41984
    cudaFuncSetAttribute(k_main, cudaFuncAttributeMaxDynamicSharedMemorySize, SM1);
    k_main<<<BS + 1, 256, SM1>>>(x, A1, A2, p);

    const int SM2 = 5 * T * 8 + 2 * (CAPT + 8) * 16;  // 163840 + 33024 = 196864
    cudaFuncSetAttribute(k_final, cudaFuncAttributeMaxDynamicSharedMemorySize, SM2);
    k_final<<<dim3(8, BS), 256, SM2>>>((float*)d_out);
}